// round 8
// baseline (speedup 1.0000x reference)
#include <cuda_runtime.h>
#include <cstdint>

// SSIM loss, separable Gaussian 11x11 on fields {s,d,s^2,d^2}, s=x+y, d=x-y.
// R7 pipeline (4 CTAs/SM, 32-slot ring, cp.async depth-2) + templated vertical
// ring-slot bases (all LDS become base+imm) + compiler-visible f32x2 packing.

namespace {
constexpr int WI = 512, HI = 512;
constexpr int SW = 64;              // strip width
constexpr int CH = 16;              // rows per chunk
constexpr int NCH = 4;              // output chunks per block (64 rows)
constexpr int RAWW = 84;            // raw row stride in floats (80 used)
constexpr int RW4 = 64;             // ring row stride in float4
constexpr float C1c = 1e-4f;
constexpr float C2c = 9e-4f;
constexpr double NPIX = 25165824.0; // 32*3*512*512
constexpr unsigned NBLK = 8 * 8 * 96;
}

__device__ double g_accum;
__device__ unsigned g_done;

using u64 = unsigned long long;

__device__ __forceinline__ u64 pk(float a, float b) {
    union { float2 f; u64 u; } c; c.f.x = a; c.f.y = b; return c.u;
}
__device__ __forceinline__ void upk(float& a, float& b, u64 v) {
    union { float2 f; u64 u; } c; c.u = v; a = c.f.x; b = c.f.y;
}
__device__ __forceinline__ u64 ffma2(u64 a, u64 b, u64 c) {
    u64 d; asm("fma.rn.f32x2 %0, %1, %2, %3;" : "=l"(d) : "l"(a), "l"(b), "l"(c));
    return d;
}
__device__ __forceinline__ u64 fmul2(u64 a, u64 b) {
    u64 d; asm("mul.rn.f32x2 %0, %1, %2;" : "=l"(d) : "l"(a), "l"(b));
    return d;
}
__device__ __forceinline__ int SWZ4(int c) { return c ^ (((c) >> 3) & 7); }

__device__ __forceinline__ void cpasync16(uint32_t dst, const void* src, int srcsize) {
    asm volatile("cp.async.cg.shared.global [%0], [%1], 16, %2;"
                 :: "r"(dst), "l"(src), "r"(srcsize) : "memory");
}
#define CP_COMMIT()  asm volatile("cp.async.commit_group;" ::: "memory")
#define CP_WAIT(N)   asm volatile("cp.async.wait_group %0;" :: "n"(N) : "memory")

// Vertical 11-tap conv over 14 ring slots -> 4 output rows + SSIM accumulate.
// SB = starting ring slot (mod 32), compile-time -> all LDS are base+imm.
template <int SB>
__device__ __forceinline__ void vertT(const float4* __restrict__ ring, int vswz,
                                      const u64* wp, float& acc)
{
    u64 aSD[4] = {0ull, 0ull, 0ull, 0ull};
    u64 aSQ[4] = {0ull, 0ull, 0ull, 0ull};
    #pragma unroll
    for (int r = 0; r < 14; r++) {
        const int slot = (SB + r) & 31;               // compile-time
        ulonglong2 v = *reinterpret_cast<const ulonglong2*>(ring + slot * RW4 + vswz);
        #pragma unroll
        for (int o = 0; o < 4; o++) {
            const int t = r - o;
            if (t >= 0 && t <= 10) {
                const int m = (t < 6) ? t : 10 - t;
                aSD[o] = ffma2(v.x, wp[m], aSD[o]);
                aSQ[o] = ffma2(v.y, wp[m], aSQ[o]);
            }
        }
    }
    #pragma unroll
    for (int o = 0; o < 4; o++) {
        float mus_sq, mud_sq, es, ed;
        upk(mus_sq, mud_sq, fmul2(aSD[o], aSD[o]));
        upk(es, ed, aSQ[o]);
        const float mu12  = 0.25f * (mus_sq - mud_sq);   // mu1*mu2
        const float musum = 0.5f  * (mus_sq + mud_sq);   // mu1^2+mu2^2
        const float cross = 0.25f * (es - ed);           // conv(x*y)
        const float sqsum = 0.5f  * (es + ed);           // conv(x^2)+conv(y^2)
        const float sigma12 = cross - mu12;
        const float sigsum  = sqsum - musum;
        const float num = (2.f * mu12 + C1c) * (2.f * sigma12 + C2c);
        const float den = (musum + C1c) * (sigsum + C2c);
        acc += __fdividef(num, den);
    }
}

__global__ void __launch_bounds__(256, 4) ssim_main(const float* __restrict__ img1,
                                                    const float* __restrict__ img2,
                                                    float* __restrict__ out)
{
    __shared__ float Araw[2][CH][RAWW];   // raw img1 rows (double buffer)
    __shared__ float Braw[2][CH][RAWW];   // raw img2 rows
    __shared__ float4 Ring[32][RW4];      // {S,D,S2,D2} per px
    __shared__ float wsum[8];

    const float Wf[6] = {0.00102838f, 0.00759877f, 0.03600077f,
                         0.10936070f, 0.21300552f, 0.26601174f};
    u64 wp[6];
    #pragma unroll
    for (int i = 0; i < 6; i++) wp[i] = pk(Wf[i], Wf[i]);

    const int tid   = threadIdx.x;
    const int x0    = blockIdx.x * SW;
    const int segY  = blockIdx.y * (CH * NCH);
    const int plane = blockIdx.z;
    const float* p1 = img1 + (size_t)plane * (size_t)(WI * HI);
    const float* p2 = img2 + (size_t)plane * (size_t)(WI * HI);

    uint32_t uA, uB;
    { uint32_t t;
      asm("{ .reg .u64 x; cvta.to.shared.u64 x, %1; cvt.u32.u64 %0, x; }"
          : "=r"(t) : "l"(&Araw[0][0][0])); uA = t;
      asm("{ .reg .u64 x; cvta.to.shared.u64 x, %1; cvt.u32.u64 %0, x; }"
          : "=r"(t) : "l"(&Braw[0][0][0])); uB = t; }

    const int hrow = tid >> 4;           // 0..15
    const int hcg  = tid & 15;           // 0..15 (4 outputs each)
    const int vx   = tid & 63;
    const int vrg  = tid >> 6;           // 0..3
    const int vswz = SWZ4(vx);
    const float4* ringp = &Ring[0][0];

    // ---- hoisted per-thread cp.async geometry (chunk-invariant) ----
    int   cRi[3], cGxi[3];
    bool  cValid[3], cColOK[3];
    const float* cBase[3];
    uint32_t cDst[3];
    #pragma unroll
    for (int i = 0; i < 3; i++) {
        int u = tid + i * 256;
        cValid[i] = (u < 640);
        int im = (u >= 320) ? 1 : 0;
        int v  = u - im * 320;
        int r  = v / 20;
        int c4 = v - r * 20;
        cRi[i]   = r;
        cGxi[i]  = x0 - 8 + c4 * 4;
        cColOK[i] = ((unsigned)cGxi[i] < (unsigned)WI);
        cBase[i] = im ? p2 : p1;
        cDst[i]  = (im ? uB : uA) + (uint32_t)((r * RAWW + c4 * 4) * 4);
    }

    float acc = 0.f;

    auto issueChunk = [&](int c) {
        const int bufOff = (c & 1) * (CH * RAWW * 4);
        const int yB = segY + c * CH - 5;
        #pragma unroll
        for (int i = 0; i < 3; i++) {
            if (cValid[i]) {
                int yy = yB + cRi[i];
                bool inb = cColOK[i] && ((unsigned)yy < (unsigned)HI);
                const float* src = cBase[i] +
                    (size_t)(inb ? yy : 0) * WI + (inb ? cGxi[i] : 0);
                cpasync16(cDst[i] + bufOff, src, inb ? 16 : 0);
            }
        }
        CP_COMMIT();
    };

    // horizontal conv of chunk p (compile-time): raw -> ring
    // Only staged px 3..16 carry taps: .64(px2-3) + 3x.128(px4-15) + .64(px16-17).
    auto horiz = [&](int p) {
        const int buf  = p & 1;
        const int slot = (((p & 1) << 4) + 27 + hrow) & 31;   // (16p-5+hrow) mod 32
        const float* rA = &Araw[buf][hrow][hcg * 4];
        const float* rB = &Braw[buf][hrow][hcg * 4];

        u64 aSD[4] = {0ull, 0ull, 0ull, 0ull};
        u64 aSQ[4] = {0ull, 0ull, 0ull, 0ull};

        auto tap = [&](int q, float a, float b) {   // q = staged px index (3..16)
            const u64 sd = pk(a + b, a - b);
            const u64 sq = fmul2(sd, sd);
            #pragma unroll
            for (int o = 0; o < 4; o++) {
                const int t = q - 3 - o;
                if (t >= 0 && t <= 10) {
                    const int m = (t < 6) ? t : 10 - t;
                    aSD[o] = ffma2(sd, wp[m], aSD[o]);
                    aSQ[o] = ffma2(sq, wp[m], aSQ[o]);
                }
            }
        };

        {   // px 3
            float2 a = *reinterpret_cast<const float2*>(rA + 2);
            float2 b = *reinterpret_cast<const float2*>(rB + 2);
            tap(3, a.y, b.y);
        }
        #pragma unroll
        for (int g = 0; g < 3; g++) {   // px 4..15
            float4 a = *reinterpret_cast<const float4*>(rA + 4 + g * 4);
            float4 b = *reinterpret_cast<const float4*>(rB + 4 + g * 4);
            tap(4 + g * 4 + 0, a.x, b.x);
            tap(4 + g * 4 + 1, a.y, b.y);
            tap(4 + g * 4 + 2, a.z, b.z);
            tap(4 + g * 4 + 3, a.w, b.w);
        }
        {   // px 16
            float2 a = *reinterpret_cast<const float2*>(rA + 16);
            float2 b = *reinterpret_cast<const float2*>(rB + 16);
            tap(16, a.x, b.x);
        }

        #pragma unroll
        for (int o = 0; o < 4; o++) {
            ulonglong2 st; st.x = aSD[o]; st.y = aSQ[o];
            *reinterpret_cast<ulonglong2*>(&Ring[slot][SWZ4(hcg * 4 + o)]) = st;
        }
    };

    // ---- prologue ----
    issueChunk(0);
    issueChunk(1);
    CP_WAIT(1);
    __syncthreads();
    horiz(0);
    __syncthreads();
    issueChunk(2);

    // ---- pipelined main loop (fully unrolled) ----
    #pragma unroll
    for (int k = 0; k < NCH; k++) {
        if (k < 3) { CP_WAIT(1); } else { CP_WAIT(0); }   // g_{k+1} done
        __syncthreads();                                   // raw visible; ring reads done
        horiz(k + 1);
        __syncthreads();
        if (k == 0) issueChunk(3);
        if (k == 1) issueChunk(4);
        // vertical for chunk k: SB = (16k + 27 + 4*vrg) & 31, compile-time per arm
        if ((k & 1) == 0) {
            if      (vrg == 0) vertT<27>(ringp, vswz, wp, acc);
            else if (vrg == 1) vertT<31>(ringp, vswz, wp, acc);
            else if (vrg == 2) vertT<3 >(ringp, vswz, wp, acc);
            else               vertT<7 >(ringp, vswz, wp, acc);
        } else {
            if      (vrg == 0) vertT<11>(ringp, vswz, wp, acc);
            else if (vrg == 1) vertT<15>(ringp, vswz, wp, acc);
            else if (vrg == 2) vertT<19>(ringp, vswz, wp, acc);
            else               vertT<23>(ringp, vswz, wp, acc);
        }
    }

    // ---- block reduction -> one double atomic per block ----
    #pragma unroll
    for (int off = 16; off > 0; off >>= 1)
        acc += __shfl_down_sync(0xffffffffu, acc, off);
    if ((tid & 31) == 0) wsum[tid >> 5] = acc;
    __syncthreads();
    if (tid == 0) {
        float s = 0.f;
        #pragma unroll
        for (int i = 0; i < 8; i++) s += wsum[i];
        atomicAdd(&g_accum, (double)s);
        __threadfence();
        unsigned t = atomicAdd(&g_done, 1u);
        if (t == NBLK - 1) {
            double tot = atomicAdd(&g_accum, 0.0);
            out[0] = (float)(1.0 - tot * (1.0 / NPIX));
            g_accum = 0.0;
            g_done  = 0u;
        }
    }
}

extern "C" void kernel_launch(void* const* d_in, const int* in_sizes, int n_in,
                              void* d_out, int out_size) {
    (void)in_sizes; (void)n_in; (void)out_size;
    const float* img1 = (const float*)d_in[0];
    const float* img2 = (const float*)d_in[1];
    ssim_main<<<dim3(WI / SW, HI / (CH * NCH), 96), 256>>>(img1, img2, (float*)d_out);
}

// round 9
// speedup vs baseline: 1.1349x; 1.1349x over previous
#include <cuda_runtime.h>
#include <cstdint>

// SSIM loss, separable Gaussian 11x11 on fields {s,d,s^2,d^2}, s=x+y, d=x-y.
// 44-slot ring; vertical = two 32-row passes, 8 rows/thread on all 256 threads
// with runtime-interleaved slot addressing. Single raw buffer + cp.async.
// Horizontal phases have compile-time slot bases (no wraps by construction).

namespace {
constexpr int WI = 512, HI = 512;
constexpr int SW = 64;              // strip width
constexpr int CH = 16;              // rows per staged chunk
constexpr int RAWW = 80;            // raw row stride in floats
constexpr int RW4 = 64;             // ring row stride in float4
constexpr int NSLOT = 44;
constexpr float C1c = 1e-4f;
constexpr float C2c = 9e-4f;
constexpr double NPIX = 25165824.0; // 32*3*512*512
constexpr unsigned NBLK = 8 * 8 * 96;
}

__device__ double g_accum;
__device__ unsigned g_done;

using u64 = unsigned long long;

__device__ __forceinline__ u64 pk(float a, float b) {
    union { float2 f; u64 u; } c; c.f.x = a; c.f.y = b; return c.u;
}
__device__ __forceinline__ void upk(float& a, float& b, u64 v) {
    union { float2 f; u64 u; } c; c.u = v; a = c.f.x; b = c.f.y;
}
__device__ __forceinline__ u64 ffma2(u64 a, u64 b, u64 c) {
    u64 d; asm("fma.rn.f32x2 %0, %1, %2, %3;" : "=l"(d) : "l"(a), "l"(b), "l"(c));
    return d;
}
__device__ __forceinline__ u64 fmul2(u64 a, u64 b) {
    u64 d; asm("mul.rn.f32x2 %0, %1, %2;" : "=l"(d) : "l"(a), "l"(b));
    return d;
}
__device__ __forceinline__ int SWZ4(int c) { return c ^ (((c) >> 3) & 7); }

__device__ __forceinline__ void cpasync16(uint32_t dst, const void* src, int srcsize) {
    asm volatile("cp.async.cg.shared.global [%0], [%1], 16, %2;"
                 :: "r"(dst), "l"(src), "r"(srcsize) : "memory");
}
#define CP_COMMIT()  asm volatile("cp.async.commit_group;" ::: "memory")
#define CP_WAIT0()   asm volatile("cp.async.wait_group 0;" ::: "memory")

__global__ void __launch_bounds__(256, 4) ssim_main(const float* __restrict__ img1,
                                                    const float* __restrict__ img2,
                                                    float* __restrict__ out)
{
    __shared__ float Araw[CH][RAWW];     // raw img1 rows (single buffer)
    __shared__ float Braw[CH][RAWW];     // raw img2 rows
    __shared__ float4 Ring[NSLOT][RW4];  // {S,D,S2,D2} per px
    __shared__ float wsum[8];

    const float Wf[6] = {0.00102838f, 0.00759877f, 0.03600077f,
                         0.10936070f, 0.21300552f, 0.26601174f};
    u64 wp[6];
    #pragma unroll
    for (int i = 0; i < 6; i++) wp[i] = pk(Wf[i], Wf[i]);

    const int tid   = threadIdx.x;
    const int x0    = blockIdx.x * SW;
    const int segY  = blockIdx.y * 64;
    const int plane = blockIdx.z;
    const float* p1 = img1 + (size_t)plane * (size_t)(WI * HI);
    const float* p2 = img2 + (size_t)plane * (size_t)(WI * HI);

    uint32_t uA, uB;
    { uint32_t t;
      asm("{ .reg .u64 x; cvta.to.shared.u64 x, %1; cvt.u32.u64 %0, x; }"
          : "=r"(t) : "l"(&Araw[0][0])); uA = t;
      asm("{ .reg .u64 x; cvta.to.shared.u64 x, %1; cvt.u32.u64 %0, x; }"
          : "=r"(t) : "l"(&Braw[0][0])); uB = t; }

    const int hrow = tid >> 4;           // 0..15
    const int hcg  = tid & 15;           // 0..15 (4 outputs each)
    const int vx   = tid & 63;
    const int vrg  = tid >> 6;           // 0..3
    const int vswz = SWZ4(vx);
    const float4* ringp = &Ring[0][0];

    // ---- hoisted per-thread cp.async geometry (chunk-invariant) ----
    int   cRi[3], cGxi[3];
    bool  cValid[3], cColOK[3];
    const float* cBase[3];
    uint32_t cDst[3];
    #pragma unroll
    for (int i = 0; i < 3; i++) {
        int u = tid + i * 256;
        cValid[i] = (u < 640);
        int im = (u >= 320) ? 1 : 0;
        int v  = u - im * 320;
        int r  = v / 20;
        int c4 = v - r * 20;
        cRi[i]   = r;
        cGxi[i]  = x0 - 8 + c4 * 4;
        cColOK[i] = ((unsigned)cGxi[i] < (unsigned)WI);
        cBase[i] = im ? p2 : p1;
        cDst[i]  = (im ? uB : uA) + (uint32_t)((r * RAWW + c4 * 4) * 4);
    }

    float acc = 0.f;

    auto issueChunk = [&](int c) {
        const int yB = segY + c * CH - 5;
        #pragma unroll
        for (int i = 0; i < 3; i++) {
            if (cValid[i]) {
                int yy = yB + cRi[i];
                bool inb = cColOK[i] && ((unsigned)yy < (unsigned)HI);
                const float* src = cBase[i] +
                    (size_t)(inb ? yy : 0) * WI + (inb ? cGxi[i] : 0);
                cpasync16(cDst[i], src, inb ? 16 : 0);
            }
        }
        CP_COMMIT();
    };

    // horizontal conv phase: raw rows [raw0, raw0+nRows) -> ring slots
    // slotBase..slotBase+nRows-1 (no wrap by construction).
    auto hz = [&](int slotBase, int raw0, int nRows) {
        if (hrow >= nRows) return;
        const int slot = slotBase + hrow;
        const float* rA = &Araw[raw0 + hrow][hcg * 4];
        const float* rB = &Braw[raw0 + hrow][hcg * 4];

        u64 aSD[4] = {0ull, 0ull, 0ull, 0ull};
        u64 aSQ[4] = {0ull, 0ull, 0ull, 0ull};

        auto tap = [&](int q, float a, float b) {   // q = staged px index (3..16)
            const u64 sd = pk(a + b, a - b);
            const u64 sq = fmul2(sd, sd);
            #pragma unroll
            for (int o = 0; o < 4; o++) {
                const int t = q - 3 - o;
                if (t >= 0 && t <= 10) {
                    const int m = (t < 6) ? t : 10 - t;
                    aSD[o] = ffma2(sd, wp[m], aSD[o]);
                    aSQ[o] = ffma2(sq, wp[m], aSQ[o]);
                }
            }
        };

        {   // px 3
            float2 a = *reinterpret_cast<const float2*>(rA + 2);
            float2 b = *reinterpret_cast<const float2*>(rB + 2);
            tap(3, a.y, b.y);
        }
        #pragma unroll
        for (int g = 0; g < 3; g++) {   // px 4..15
            float4 a = *reinterpret_cast<const float4*>(rA + 4 + g * 4);
            float4 b = *reinterpret_cast<const float4*>(rB + 4 + g * 4);
            tap(4 + g * 4 + 0, a.x, b.x);
            tap(4 + g * 4 + 1, a.y, b.y);
            tap(4 + g * 4 + 2, a.z, b.z);
            tap(4 + g * 4 + 3, a.w, b.w);
        }
        {   // px 16
            float2 a = *reinterpret_cast<const float2*>(rA + 16);
            float2 b = *reinterpret_cast<const float2*>(rB + 16);
            tap(16, a.x, b.x);
        }

        #pragma unroll
        for (int o = 0; o < 4; o++) {
            ulonglong2 st; st.x = aSD[o]; st.y = aSQ[o];
            *reinterpret_cast<ulonglong2*>(&Ring[slot][SWZ4(hcg * 4 + o)]) = st;
        }
    };

    // vertical: 8 output rows/thread over 18 ring slots, runtime slot walk.
    // m = 0: slots vrg*8 .. vrg*8+17 (no wrap). m = 1: base 32+vrg*8 mod 44.
    auto vert = [&](int m) {
        int s = m * 32 + vrg * 8;
        if (s >= NSLOT) s -= NSLOT;
        u64 aSD[8], aSQ[8];
        #pragma unroll
        for (int o = 0; o < 8; o++) { aSD[o] = 0ull; aSQ[o] = 0ull; }
        #pragma unroll
        for (int r = 0; r < 18; r++) {
            ulonglong2 v = *reinterpret_cast<const ulonglong2*>(ringp + s * RW4 + vswz);
            s++; if (s == NSLOT) s = 0;
            #pragma unroll
            for (int o = 0; o < 8; o++) {
                const int t = r - o;
                if (t >= 0 && t <= 10) {
                    const int mm = (t < 6) ? t : 10 - t;
                    aSD[o] = ffma2(v.x, wp[mm], aSD[o]);
                    aSQ[o] = ffma2(v.y, wp[mm], aSQ[o]);
                }
            }
        }
        #pragma unroll
        for (int o = 0; o < 8; o++) {
            float mus_sq, mud_sq, es, ed;
            upk(mus_sq, mud_sq, fmul2(aSD[o], aSD[o]));
            upk(es, ed, aSQ[o]);
            const float mu12  = 0.25f * (mus_sq - mud_sq);   // mu1*mu2
            const float musum = 0.5f  * (mus_sq + mud_sq);   // mu1^2+mu2^2
            const float cross = 0.25f * (es - ed);           // conv(x*y)
            const float sqsum = 0.5f  * (es + ed);           // conv(x^2)+conv(y^2)
            const float sigma12 = cross - mu12;
            const float sigsum  = sqsum - musum;
            const float num = (2.f * mu12 + C1c) * (2.f * sigma12 + C2c);
            const float den = (musum + C1c) * (sigsum + C2c);
            acc += __fdividef(num, den);
        }
    };

    // ---- phase schedule (rows t are segment-local; slot(t) = (t+5) mod 44) ----
    issueChunk(0); CP_WAIT0(); __syncthreads();
    hz(0, 0, 16);                    // t -5..10  -> slots 0..15
    __syncthreads();
    issueChunk(1); CP_WAIT0(); __syncthreads();
    hz(16, 0, 16);                   // t 11..26  -> slots 16..31
    __syncthreads();
    issueChunk(2); CP_WAIT0(); __syncthreads();
    hz(32, 0, 12);                   // t 27..38  -> slots 32..43
    __syncthreads();
    vert(0);                         // rows 0..31, reads slots 0..41
    __syncthreads();                 // WAR: vert(0) reads before slot 0..3 reuse
    hz(0, 12, 4);                    // t 39..42  -> slots 0..3 (raw rows 12..15)
    __syncthreads();
    issueChunk(3); CP_WAIT0(); __syncthreads();
    hz(4, 0, 16);                    // t 43..58  -> slots 4..19
    __syncthreads();
    issueChunk(4); CP_WAIT0(); __syncthreads();
    hz(20, 0, 10);                   // t 59..68  -> slots 20..29
    __syncthreads();
    vert(1);                         // rows 32..63, reads slots 32..43, 0..29

    // ---- block reduction -> one double atomic per block ----
    #pragma unroll
    for (int off = 16; off > 0; off >>= 1)
        acc += __shfl_down_sync(0xffffffffu, acc, off);
    if ((tid & 31) == 0) wsum[tid >> 5] = acc;
    __syncthreads();
    if (tid == 0) {
        float s = 0.f;
        #pragma unroll
        for (int i = 0; i < 8; i++) s += wsum[i];
        atomicAdd(&g_accum, (double)s);
        __threadfence();
        unsigned t = atomicAdd(&g_done, 1u);
        if (t == NBLK - 1) {
            double tot = atomicAdd(&g_accum, 0.0);
            out[0] = (float)(1.0 - tot * (1.0 / NPIX));
            g_accum = 0.0;
            g_done  = 0u;
        }
    }
}

extern "C" void kernel_launch(void* const* d_in, const int* in_sizes, int n_in,
                              void* d_out, int out_size) {
    (void)in_sizes; (void)n_in; (void)out_size;
    const float* img1 = (const float*)d_in[0];
    const float* img2 = (const float*)d_in[1];
    ssim_main<<<dim3(WI / SW, HI / 64, 96), 256>>>(img1, img2, (float*)d_out);
}

// round 10
// speedup vs baseline: 1.2531x; 1.1042x over previous
#include <cuda_runtime.h>
#include <cstdint>

// SSIM loss, separable Gaussian 11x11 on fields {s,d,s^2,d^2}, s=x+y, d=x-y.
// Warp-private raw rows: warp w copies AND reads raw rows {2w,2w+1}, so the
// single 16-row staging buffer needs no block barriers and each warp issues
// its next-chunk cp.async right after consuming its rows (latency hidden).
// 44-slot ring, vertical 8 rows/thread (2 passes of 32 rows, all 256 threads,
// runtime slot walk). 4 CTAs/SM. Only 4 block barriers.

namespace {
constexpr int WI = 512, HI = 512;
constexpr int SW = 64;              // strip width
constexpr int CH = 16;              // rows per staged chunk
constexpr int RAWW = 80;            // raw row stride in floats
constexpr int RW4 = 64;             // ring row stride in float4
constexpr int NSLOT = 44;
constexpr float C1c = 1e-4f;
constexpr float C2c = 9e-4f;
constexpr double NPIX = 25165824.0; // 32*3*512*512
constexpr unsigned NBLK = 8 * 8 * 96;
}

__device__ double g_accum;
__device__ unsigned g_done;

using u64 = unsigned long long;

__device__ __forceinline__ u64 pk(float a, float b) {
    union { float2 f; u64 u; } c; c.f.x = a; c.f.y = b; return c.u;
}
__device__ __forceinline__ void upk(float& a, float& b, u64 v) {
    union { float2 f; u64 u; } c; c.u = v; a = c.f.x; b = c.f.y;
}
__device__ __forceinline__ u64 ffma2(u64 a, u64 b, u64 c) {
    u64 d; asm("fma.rn.f32x2 %0, %1, %2, %3;" : "=l"(d) : "l"(a), "l"(b), "l"(c));
    return d;
}
__device__ __forceinline__ u64 fmul2(u64 a, u64 b) {
    u64 d; asm("mul.rn.f32x2 %0, %1, %2;" : "=l"(d) : "l"(a), "l"(b));
    return d;
}
__device__ __forceinline__ int SWZ4(int c) { return c ^ (((c) >> 3) & 7); }

__device__ __forceinline__ void cpasync16(uint32_t dst, const void* src, int srcsize) {
    asm volatile("cp.async.cg.shared.global [%0], [%1], 16, %2;"
                 :: "r"(dst), "l"(src), "r"(srcsize) : "memory");
}
#define CP_COMMIT()  asm volatile("cp.async.commit_group;" ::: "memory")
#define CP_WAIT0()   asm volatile("cp.async.wait_group 0;" ::: "memory")

__global__ void __launch_bounds__(256, 4) ssim_main(const float* __restrict__ img1,
                                                    const float* __restrict__ img2,
                                                    float* __restrict__ out)
{
    __shared__ float Araw[CH][RAWW];     // raw img1 rows (warp-private pairs)
    __shared__ float Braw[CH][RAWW];     // raw img2 rows
    __shared__ float4 Ring[NSLOT][RW4];  // {S,D,S2,D2} per px
    __shared__ float wsum[8];

    const float Wf[6] = {0.00102838f, 0.00759877f, 0.03600077f,
                         0.10936070f, 0.21300552f, 0.26601174f};
    u64 wp[6];
    #pragma unroll
    for (int i = 0; i < 6; i++) wp[i] = pk(Wf[i], Wf[i]);

    const int tid   = threadIdx.x;
    const int x0    = blockIdx.x * SW;
    const int segY  = blockIdx.y * 64;
    const int plane = blockIdx.z;
    const float* p1 = img1 + (size_t)plane * (size_t)(WI * HI);
    const float* p2 = img2 + (size_t)plane * (size_t)(WI * HI);

    uint32_t uA, uB;
    { uint32_t t;
      asm("{ .reg .u64 x; cvta.to.shared.u64 x, %1; cvt.u32.u64 %0, x; }"
          : "=r"(t) : "l"(&Araw[0][0])); uA = t;
      asm("{ .reg .u64 x; cvta.to.shared.u64 x, %1; cvt.u32.u64 %0, x; }"
          : "=r"(t) : "l"(&Braw[0][0])); uB = t; }

    const int hrow = tid >> 4;           // 0..15 (warp w owns rows 2w,2w+1)
    const int hcg  = tid & 15;           // 0..15 (4 outputs each)
    const int w    = tid >> 5;           // warp id
    const int lane = tid & 31;
    const int vx   = tid & 63;
    const int vrg  = tid >> 6;           // 0..3
    const int vswz = SWZ4(vx);
    const float4* ringp = &Ring[0][0];

    // ---- warp-private copy geometry: 80 16B-units per warp (2 rows x 2 imgs x 20) ----
    int   myRow[3], myGx[3];
    bool  uvalid[3], colOK[3];
    const float* pImg[3];
    uint32_t dstA[3];
    #pragma unroll
    for (int i = 0; i < 3; i++) {
        int u = lane + 32 * i;
        uvalid[i] = (u < 80);
        int row01 = u / 40;
        int rem   = u - 40 * row01;
        int im    = rem / 20;
        int c4    = rem - 20 * im;
        myRow[i]  = 2 * w + row01;
        myGx[i]   = x0 - 8 + c4 * 4;
        colOK[i]  = ((unsigned)myGx[i] < (unsigned)WI);
        pImg[i]   = im ? p2 : p1;
        dstA[i]   = (im ? uB : uA) + (uint32_t)((myRow[i] * RAWW + c4 * 4) * 4);
    }

    float acc = 0.f;

    // issue this warp's rows of chunk c (only rows < rowCount; caller guards warp)
    auto issueMy = [&](int c) {
        const int yB = segY + c * CH - 5;
        #pragma unroll
        for (int i = 0; i < 3; i++) {
            if (uvalid[i]) {
                int yy = yB + myRow[i];
                bool inb = colOK[i] && ((unsigned)yy < (unsigned)HI);
                const float* src = pImg[i] +
                    (inb ? (size_t)yy * (size_t)WI + (size_t)myGx[i] : (size_t)0);
                cpasync16(dstA[i], src, inb ? 16 : 0);
            }
        }
        CP_COMMIT();
    };

    // horizontal conv of this thread's raw row -> ring slot (compile-time slot math
    // at each call site). Loads .64 + 3x.128 + .64 per image (staged px 3..16).
    auto hzBody = [&](int slot) {
        const float* rA = &Araw[hrow][hcg * 4];
        const float* rB = &Braw[hrow][hcg * 4];

        u64 aSD[4] = {0ull, 0ull, 0ull, 0ull};
        u64 aSQ[4] = {0ull, 0ull, 0ull, 0ull};

        auto tap = [&](int q, float a, float b) {   // q = staged px index (3..16)
            const u64 sd = pk(a + b, a - b);
            const u64 sq = fmul2(sd, sd);
            #pragma unroll
            for (int o = 0; o < 4; o++) {
                const int t = q - 3 - o;
                if (t >= 0 && t <= 10) {
                    const int m = (t < 6) ? t : 10 - t;
                    aSD[o] = ffma2(sd, wp[m], aSD[o]);
                    aSQ[o] = ffma2(sq, wp[m], aSQ[o]);
                }
            }
        };

        {   // px 3
            float2 a = *reinterpret_cast<const float2*>(rA + 2);
            float2 b = *reinterpret_cast<const float2*>(rB + 2);
            tap(3, a.y, b.y);
        }
        #pragma unroll
        for (int g = 0; g < 3; g++) {   // px 4..15
            float4 a = *reinterpret_cast<const float4*>(rA + 4 + g * 4);
            float4 b = *reinterpret_cast<const float4*>(rB + 4 + g * 4);
            tap(4 + g * 4 + 0, a.x, b.x);
            tap(4 + g * 4 + 1, a.y, b.y);
            tap(4 + g * 4 + 2, a.z, b.z);
            tap(4 + g * 4 + 3, a.w, b.w);
        }
        {   // px 16
            float2 a = *reinterpret_cast<const float2*>(rA + 16);
            float2 b = *reinterpret_cast<const float2*>(rB + 16);
            tap(16, a.x, b.x);
        }

        #pragma unroll
        for (int o = 0; o < 4; o++) {
            ulonglong2 st; st.x = aSD[o]; st.y = aSQ[o];
            *reinterpret_cast<ulonglong2*>(&Ring[slot][SWZ4(hcg * 4 + o)]) = st;
        }
    };

    // vertical: 8 output rows/thread over 18 ring slots, runtime slot walk.
    auto vert = [&](int m) {
        int s = m * 32 + vrg * 8;
        if (s >= NSLOT) s -= NSLOT;
        u64 aSD[8], aSQ[8];
        #pragma unroll
        for (int o = 0; o < 8; o++) { aSD[o] = 0ull; aSQ[o] = 0ull; }
        #pragma unroll
        for (int r = 0; r < 18; r++) {
            ulonglong2 v = *reinterpret_cast<const ulonglong2*>(ringp + s * RW4 + vswz);
            s++; if (s == NSLOT) s = 0;
            #pragma unroll
            for (int o = 0; o < 8; o++) {
                const int t = r - o;
                if (t >= 0 && t <= 10) {
                    const int mm = (t < 6) ? t : 10 - t;
                    aSD[o] = ffma2(v.x, wp[mm], aSD[o]);
                    aSQ[o] = ffma2(v.y, wp[mm], aSQ[o]);
                }
            }
        }
        #pragma unroll
        for (int o = 0; o < 8; o++) {
            float mus_sq, mud_sq, es, ed;
            upk(mus_sq, mud_sq, fmul2(aSD[o], aSD[o]));
            upk(es, ed, aSQ[o]);
            const float mu12  = 0.25f * (mus_sq - mud_sq);   // mu1*mu2
            const float musum = 0.5f  * (mus_sq + mud_sq);   // mu1^2+mu2^2
            const float cross = 0.25f * (es - ed);           // conv(x*y)
            const float sqsum = 0.5f  * (es + ed);           // conv(x^2)+conv(y^2)
            const float sigma12 = cross - mu12;
            const float sigsum  = sqsum - musum;
            const float num = (2.f * mu12 + C1c) * (2.f * sigma12 + C2c);
            const float den = (musum + C1c) * (sigsum + C2c);
            acc += __fdividef(num, den);
        }
    };

    // ---- schedule (segment-local rows t; slot(t) = (t+5) mod 44) ----
    issueMy(0);                              // chunk 0: t -5..10

    CP_WAIT0(); __syncwarp();
    hzBody(0 + hrow);                        // c0 -> slots 0..15
    issueMy(1);                              // chunk 1: t 11..26

    CP_WAIT0(); __syncwarp();
    hzBody(16 + hrow);                       // c1 -> slots 16..31
    issueMy(2);                              // chunk 2: t 27..42

    CP_WAIT0(); __syncwarp();                // all warps wait c2 (rows warp-private)
    if (hrow < 12) hzBody(32 + hrow);        // c2a (rows 0..11) -> slots 32..43
    if (w < 6) issueMy(3);                   // chunk 3 rows 0..11 (those raw rows now free)

    __syncthreads();                         // ring slots 0..43 complete
    vert(0);                                 // rows 0..31; c3 copies in flight
    __syncthreads();                         // vert(0) ring reads done

    if (w >= 6) {                            // warps 6,7: deferred c2 rows 12..15
        hzBody(hrow - 12);                   // -> slots 0..3
        issueMy(3);                          // chunk 3 rows 12..15
    }

    CP_WAIT0(); __syncwarp();                // own c3 rows arrived
    hzBody(4 + hrow);                        // c3 -> slots 4..19
    if (w < 5) issueMy(4);                   // chunk 4: t 59..68 (rows 0..9)

    if (w < 5) {
        CP_WAIT0(); __syncwarp();
        if (hrow < 10) hzBody(20 + hrow);    // c4 -> slots 20..29
    }

    __syncthreads();                         // ring slots {32..43, 0..29} complete
    vert(1);                                 // rows 32..63

    // ---- block reduction -> one double atomic per block ----
    #pragma unroll
    for (int off = 16; off > 0; off >>= 1)
        acc += __shfl_down_sync(0xffffffffu, acc, off);
    if ((tid & 31) == 0) wsum[tid >> 5] = acc;
    __syncthreads();
    if (tid == 0) {
        float s = 0.f;
        #pragma unroll
        for (int i = 0; i < 8; i++) s += wsum[i];
        atomicAdd(&g_accum, (double)s);
        __threadfence();
        unsigned t = atomicAdd(&g_done, 1u);
        if (t == NBLK - 1) {
            double tot = atomicAdd(&g_accum, 0.0);
            out[0] = (float)(1.0 - tot * (1.0 / NPIX));
            g_accum = 0.0;
            g_done  = 0u;
        }
    }
}

extern "C" void kernel_launch(void* const* d_in, const int* in_sizes, int n_in,
                              void* d_out, int out_size) {
    (void)in_sizes; (void)n_in; (void)out_size;
    const float* img1 = (const float*)d_in[0];
    const float* img2 = (const float*)d_in[1];
    ssim_main<<<dim3(WI / SW, HI / 64, 96), 256>>>(img1, img2, (float*)d_out);
}

// round 11
// speedup vs baseline: 1.2797x; 1.0212x over previous
#include <cuda_runtime.h>
#include <cstdint>

// SSIM loss, separable Gaussian 11x11 on fields {s,d,s^2,d^2}, s=x+y, d=x-y.
// Staging-free horizontal: reads GMEM directly (predicated .64/.128 loads,
// L1 serves the 3.5x overlapping windows), writes the 44-slot AoS ring.
// Vertical: 8 rows/thread, 2 passes of 32 rows, runtime slot walk.
// Only 3 block barriers. 4 CTAs/SM.

namespace {
constexpr int WI = 512, HI = 512;
constexpr int SW = 64;              // strip width
constexpr int RW4 = 64;             // ring row stride in float4
constexpr int NSLOT = 44;
constexpr float C1c = 1e-4f;
constexpr float C2c = 9e-4f;
constexpr double NPIX = 25165824.0; // 32*3*512*512
constexpr unsigned NBLK = 8 * 8 * 96;
}

__device__ double g_accum;
__device__ unsigned g_done;

using u64 = unsigned long long;

__device__ __forceinline__ u64 pk(float a, float b) {
    union { float2 f; u64 u; } c; c.f.x = a; c.f.y = b; return c.u;
}
__device__ __forceinline__ void upk(float& a, float& b, u64 v) {
    union { float2 f; u64 u; } c; c.u = v; a = c.f.x; b = c.f.y;
}
__device__ __forceinline__ u64 ffma2(u64 a, u64 b, u64 c) {
    u64 d; asm("fma.rn.f32x2 %0, %1, %2, %3;" : "=l"(d) : "l"(a), "l"(b), "l"(c));
    return d;
}
__device__ __forceinline__ u64 fmul2(u64 a, u64 b) {
    u64 d; asm("mul.rn.f32x2 %0, %1, %2;" : "=l"(d) : "l"(a), "l"(b));
    return d;
}
__device__ __forceinline__ int SWZ4(int c) { return c ^ (((c) >> 3) & 7); }

__global__ void __launch_bounds__(256, 4) ssim_main(const float* __restrict__ img1,
                                                    const float* __restrict__ img2,
                                                    float* __restrict__ out)
{
    __shared__ float4 Ring[NSLOT][RW4];  // {S,D,S2,D2} per px
    __shared__ float wsum[8];

    const float Wf[6] = {0.00102838f, 0.00759877f, 0.03600077f,
                         0.10936070f, 0.21300552f, 0.26601174f};
    u64 wp[6];
    #pragma unroll
    for (int i = 0; i < 6; i++) wp[i] = pk(Wf[i], Wf[i]);

    const int tid   = threadIdx.x;
    const int x0    = blockIdx.x * SW;
    const int segY  = blockIdx.y * 64;
    const int plane = blockIdx.z;
    const float* p1 = img1 + (size_t)plane * (size_t)(WI * HI);
    const float* p2 = img2 + (size_t)plane * (size_t)(WI * HI);

    const int hrow = tid >> 4;           // 0..15
    const int hcg  = tid & 15;           // 0..15 (4 outputs each)
    const int vx   = tid & 63;
    const int vrg  = tid >> 6;           // 0..3
    const int vswz = SWZ4(vx);
    const float4* ringp = &Ring[0][0];

    // column base for this thread's horizontal window; per-unit col validity
    // (units: .64@+2, .128@+4, .128@+8, .128@+12, .64@+16 — each fully in/out)
    const int gbx = x0 - 8 + hcg * 4;
    const bool cin0 = (gbx + 2  >= 0) && (gbx + 4  <= WI);
    const bool cin1 = (gbx + 4  >= 0) && (gbx + 8  <= WI);
    const bool cin2 = (gbx + 8  >= 0) && (gbx + 12 <= WI);
    const bool cin3 = (gbx + 12 >= 0) && (gbx + 16 <= WI);
    const bool cin4 = (gbx + 16 >= 0) && (gbx + 18 <= WI);

    float acc = 0.f;

    // horizontal conv of global row ty -> ring slot (direct GMEM reads)
    auto hzg = [&](int slot, int ty) {
        const bool rowIn = ((unsigned)ty < (unsigned)HI);
        const size_t ro = (size_t)(rowIn ? ty : 0) * WI;
        const float* rA = p1 + ro + gbx;
        const float* rB = p2 + ro + gbx;

        const float2 z2 = make_float2(0.f, 0.f);
        const float4 z4 = make_float4(0.f, 0.f, 0.f, 0.f);
        float2 a0 = (rowIn && cin0) ? *reinterpret_cast<const float2*>(rA + 2)  : z2;
        float2 b0 = (rowIn && cin0) ? *reinterpret_cast<const float2*>(rB + 2)  : z2;
        float4 a1 = (rowIn && cin1) ? *reinterpret_cast<const float4*>(rA + 4)  : z4;
        float4 b1 = (rowIn && cin1) ? *reinterpret_cast<const float4*>(rB + 4)  : z4;
        float4 a2 = (rowIn && cin2) ? *reinterpret_cast<const float4*>(rA + 8)  : z4;
        float4 b2 = (rowIn && cin2) ? *reinterpret_cast<const float4*>(rB + 8)  : z4;
        float4 a3 = (rowIn && cin3) ? *reinterpret_cast<const float4*>(rA + 12) : z4;
        float4 b3 = (rowIn && cin3) ? *reinterpret_cast<const float4*>(rB + 12) : z4;
        float2 a4 = (rowIn && cin4) ? *reinterpret_cast<const float2*>(rA + 16) : z2;
        float2 b4 = (rowIn && cin4) ? *reinterpret_cast<const float2*>(rB + 16) : z2;

        u64 aSD[4] = {0ull, 0ull, 0ull, 0ull};
        u64 aSQ[4] = {0ull, 0ull, 0ull, 0ull};

        auto tap = [&](int q, float a, float b) {   // q = window px index (3..16)
            const u64 sd = pk(a + b, a - b);
            const u64 sq = fmul2(sd, sd);
            #pragma unroll
            for (int o = 0; o < 4; o++) {
                const int t = q - 3 - o;
                if (t >= 0 && t <= 10) {
                    const int m = (t < 6) ? t : 10 - t;
                    aSD[o] = ffma2(sd, wp[m], aSD[o]);
                    aSQ[o] = ffma2(sq, wp[m], aSQ[o]);
                }
            }
        };

        tap(3,  a0.y, b0.y);
        tap(4,  a1.x, b1.x); tap(5,  a1.y, b1.y); tap(6,  a1.z, b1.z); tap(7,  a1.w, b1.w);
        tap(8,  a2.x, b2.x); tap(9,  a2.y, b2.y); tap(10, a2.z, b2.z); tap(11, a2.w, b2.w);
        tap(12, a3.x, b3.x); tap(13, a3.y, b3.y); tap(14, a3.z, b3.z); tap(15, a3.w, b3.w);
        tap(16, a4.x, b4.x);

        #pragma unroll
        for (int o = 0; o < 4; o++) {
            ulonglong2 st; st.x = aSD[o]; st.y = aSQ[o];
            *reinterpret_cast<ulonglong2*>(&Ring[slot][SWZ4(hcg * 4 + o)]) = st;
        }
    };

    // vertical: 8 output rows/thread over 18 ring slots, runtime slot walk
    auto vert = [&](int m) {
        int s = m * 32 + vrg * 8;
        if (s >= NSLOT) s -= NSLOT;
        u64 aSD[8], aSQ[8];
        #pragma unroll
        for (int o = 0; o < 8; o++) { aSD[o] = 0ull; aSQ[o] = 0ull; }
        #pragma unroll
        for (int r = 0; r < 18; r++) {
            ulonglong2 v = *reinterpret_cast<const ulonglong2*>(ringp + s * RW4 + vswz);
            s++; if (s == NSLOT) s = 0;
            #pragma unroll
            for (int o = 0; o < 8; o++) {
                const int t = r - o;
                if (t >= 0 && t <= 10) {
                    const int mm = (t < 6) ? t : 10 - t;
                    aSD[o] = ffma2(v.x, wp[mm], aSD[o]);
                    aSQ[o] = ffma2(v.y, wp[mm], aSQ[o]);
                }
            }
        }
        #pragma unroll
        for (int o = 0; o < 8; o++) {
            float mus_sq, mud_sq, es, ed;
            upk(mus_sq, mud_sq, fmul2(aSD[o], aSD[o]));
            upk(es, ed, aSQ[o]);
            const float mu12  = 0.25f * (mus_sq - mud_sq);   // mu1*mu2
            const float musum = 0.5f  * (mus_sq + mud_sq);   // mu1^2+mu2^2
            const float cross = 0.25f * (es - ed);           // conv(x*y)
            const float sqsum = 0.5f  * (es + ed);           // conv(x^2)+conv(y^2)
            const float sigma12 = cross - mu12;
            const float sigsum  = sqsum - musum;
            const float num = (2.f * mu12 + C1c) * (2.f * sigma12 + C2c);
            const float den = (musum + C1c) * (sigsum + C2c);
            acc += __fdividef(num, den);
        }
    };

    // ---- schedule (segment-local rows t = gy - segY; slot(t) = (t+5) mod 44) ----
    // Phase A: rows t = -5..38 (44 rows) -> slots 0..43
    hzg(0 + hrow,  segY - 5 + hrow);
    hzg(16 + hrow, segY + 11 + hrow);
    if (hrow < 12) hzg(32 + hrow, segY + 27 + hrow);
    __syncthreads();

    vert(0);                     // output rows 0..31, reads slots 0..41
    __syncthreads();             // vert(0) reads done before slot reuse

    // Phase B: rows t = 39..68 (30 rows) -> slots 0..29
    hzg(0 + hrow, segY + 39 + hrow);
    if (hrow < 14) hzg(16 + hrow, segY + 55 + hrow);
    __syncthreads();

    vert(1);                     // output rows 32..63, reads slots 32..43, 0..29

    // ---- block reduction -> one double atomic per block ----
    #pragma unroll
    for (int off = 16; off > 0; off >>= 1)
        acc += __shfl_down_sync(0xffffffffu, acc, off);
    if ((tid & 31) == 0) wsum[tid >> 5] = acc;
    __syncthreads();
    if (tid == 0) {
        float s = 0.f;
        #pragma unroll
        for (int i = 0; i < 8; i++) s += wsum[i];
        atomicAdd(&g_accum, (double)s);
        __threadfence();
        unsigned t = atomicAdd(&g_done, 1u);
        if (t == NBLK - 1) {
            double tot = atomicAdd(&g_accum, 0.0);
            out[0] = (float)(1.0 - tot * (1.0 / NPIX));
            g_accum = 0.0;
            g_done  = 0u;
        }
    }
}

extern "C" void kernel_launch(void* const* d_in, const int* in_sizes, int n_in,
                              void* d_out, int out_size) {
    (void)in_sizes; (void)n_in; (void)out_size;
    const float* img1 = (const float*)d_in[0];
    const float* img2 = (const float*)d_in[1];
    ssim_main<<<dim3(WI / SW, HI / 64, 96), 256>>>(img1, img2, (float*)d_out);
}